// round 2
// baseline (speedup 1.0000x reference)
#include <cuda_runtime.h>

// Problem constants
// B=2048, DKV=64, L=128, H=16, DT=32, KW=13, PAD=6
#define NT 512
#define SMEM_FLOATS 47872
#define SMEM_BYTES (SMEM_FLOATS * 4)

// shared-memory layout offsets (floats)
#define OFF_QB   0        // 4096   (reused as Y in phase 3: 32*129=4128)
#define OFF_KB   4096
#define OFF_VB   8192
#define OFF_ATT  12288    // 32*513 = 16416 -> ends 28704
#define OFF_IN   12288    // phase1: 64*140 = 8960 -> ends 21248 (overlays ATT, dead then)
#define OFF_CW   21248    // 26624 -> ends 47872
#define OFF_WH   28704    // 3*4096 = 12288 -> ends 40992
#define OFF_QH   40992    // 32*33 = 1056
#define OFF_KH   42048
#define OFF_VH   43104
#define OFF_SC   44160    // 1024 -> 45184
#define OFF_Y    0        // 32*129 = 4128
#define OFF_PW   28704    // 16384 -> 45088
#define OFF_FCW  4160     // 26624 -> 30784
#define OFF_Z    30784    // 8192 -> 38976

__global__ void __launch_bounds__(NT, 1)
ha_kernel(const float* __restrict__ gq, const float* __restrict__ gk, const float* __restrict__ gv,
          const float* __restrict__ cq_w, const float* __restrict__ cq_b,
          const float* __restrict__ ck_w, const float* __restrict__ ck_b,
          const float* __restrict__ cv_w, const float* __restrict__ cv_b,
          const float* __restrict__ w_qs, const float* __restrict__ w_ks, const float* __restrict__ w_vs,
          const float* __restrict__ proj_w, const float* __restrict__ proj_b,
          const float* __restrict__ fc_w, const float* __restrict__ fc_b,
          const float* __restrict__ ln_a, const float* __restrict__ ln_b,
          float* __restrict__ out)
{
    extern __shared__ float s[];
    const int tid = threadIdx.x;
    const int b = blockIdx.x;
    const size_t boff = (size_t)b * 8192;   // 64*128

    // ================= Phase 1: conv1d(q/k/v): (64,128) -> (32,128), kw=13, pad=6 =================
    {
        const int l = tid & 127;
        const int cobase = (tid >> 7) * 8;   // quarter -> 8 output channels each
        for (int m = 0; m < 3; m++) {
            const float* xin = (m == 0 ? gq : m == 1 ? gk : gv) + boff;
            const float* cw  = (m == 0 ? cq_w : m == 1 ? ck_w : cv_w);
            const float* cb  = (m == 0 ? cq_b : m == 1 ? ck_b : cv_b);
            float* dst = s + (m == 0 ? OFF_QB : m == 1 ? OFF_KB : OFF_VB);
            __syncthreads();
            // zero the 6-element pads of each 140-wide row
            for (int i = tid; i < 64 * 12; i += NT) {
                int ci = i / 12, j = i % 12;
                s[OFF_IN + ci * 140 + (j < 6 ? j : j + 128)] = 0.f;
            }
            // fill input rows (coalesced)
            for (int i = tid; i < 8192; i += NT)
                s[OFF_IN + (i >> 7) * 140 + 6 + (i & 127)] = xin[i];
            // conv weights 32*64*13
            for (int i = tid; i < 26624; i += NT) s[OFF_CW + i] = cw[i];
            __syncthreads();

            float acc[8];
            #pragma unroll
            for (int i = 0; i < 8; i++) acc[i] = __ldg(&cb[cobase + i]);
            for (int ci = 0; ci < 64; ci++) {
                const float* ir = s + OFF_IN + ci * 140 + l;          // ir[kk] = in[ci][l+kk-6]
                const float* wr = s + OFF_CW + (cobase * 64 + ci) * 13;
                #pragma unroll
                for (int kk = 0; kk < 13; kk++) {
                    float xv = ir[kk];
                    #pragma unroll
                    for (int i = 0; i < 8; i++)
                        acc[i] += xv * wr[kk + i * 832];               // (co+i)*64*13 stride
                }
            }
            #pragma unroll
            for (int i = 0; i < 8; i++) dst[(cobase + i) * 128 + l] = acc[i];
        }
    }

    // ================= Phase 2: per-head projections + attention =================
    {
        const int lane = tid & 31;
        const int wrp  = tid >> 5;   // 0..15
        const float inv_t = 0.08838834764831845f;   // 1/sqrt(128)
        for (int h = 0; h < 16; h++) {
            __syncthreads();
            const float* wq = w_qs + h * 4096;
            const float* wk = w_ks + h * 4096;
            const float* wv = w_vs + h * 4096;
            for (int i = tid; i < 4096; i += NT) {
                s[OFF_WH + i]        = wq[i];
                s[OFF_WH + 4096 + i] = wk[i];
                s[OFF_WH + 8192 + i] = wv[i];
            }
            __syncthreads();
            // qh/kh/vh: [32,32] each; qh[t][d] = sum_l qb[t][l] * w[l][d]
            #pragma unroll
            for (int m = 0; m < 3; m++) {
                const float* src = s + (m == 0 ? OFF_QB : m == 1 ? OFF_KB : OFF_VB);
                const float* W   = s + OFF_WH + m * 4096;
                float* dst       = s + (m == 0 ? OFF_QH : m == 1 ? OFF_KH : OFF_VH);
                #pragma unroll
                for (int rr = 0; rr < 2; rr++) {
                    int tt = wrp + rr * 16;
                    const float* sr = src + tt * 128;
                    float a0 = 0.f, a1 = 0.f;
                    #pragma unroll 8
                    for (int l2 = 0; l2 < 128; l2 += 2) {
                        a0 += sr[l2]     * W[l2 * 32 + lane];
                        a1 += sr[l2 + 1] * W[(l2 + 1) * 32 + lane];
                    }
                    dst[tt * 33 + lane] = a0 + a1;   // stride 33: conflict-free transposed reads
                }
            }
            __syncthreads();
            // scores[q][k] = dot(qh[q], kh[k]) / sqrt(128)
            #pragma unroll
            for (int rr = 0; rr < 2; rr++) {
                int qq = wrp + rr * 16;
                float a = 0.f;
                #pragma unroll
                for (int d = 0; d < 32; d++)
                    a += s[OFF_QH + qq * 33 + d] * s[OFF_KH + lane * 33 + d];
                s[OFF_SC + qq * 32 + lane] = a * inv_t;
            }
            __syncthreads();
            // softmax over k (rows handled one-per-warp)
            #pragma unroll
            for (int rr = 0; rr < 2; rr++) {
                int r = wrp + rr * 16;
                float x = s[OFF_SC + r * 32 + lane];
                float mx = x;
                #pragma unroll
                for (int o = 16; o > 0; o >>= 1)
                    mx = fmaxf(mx, __shfl_xor_sync(0xffffffffu, mx, o));
                float e = __expf(x - mx);
                float sum = e;
                #pragma unroll
                for (int o = 16; o > 0; o >>= 1)
                    sum += __shfl_xor_sync(0xffffffffu, sum, o);
                s[OFF_SC + r * 32 + lane] = e / sum;
            }
            __syncthreads();
            // out = attn @ vh -> att_cat[t][h*32+d]  (row stride 513: conflict-free in proj)
            #pragma unroll
            for (int rr = 0; rr < 2; rr++) {
                int tt = wrp + rr * 16;
                float a = 0.f;
                #pragma unroll
                for (int kk = 0; kk < 32; kk++)
                    a += s[OFF_SC + tt * 32 + kk] * s[OFF_VH + kk * 33 + lane];
                s[OFF_ATT + tt * 513 + h * 32 + lane] = a;
            }
        }
    }

    // ================= Phase 3: proj  y[t][m] = att[t][:512] . proj_w[m][:512] + b[m] =================
    {
        const int lane = tid & 31;
        const int wrp  = tid >> 5;
        for (int mc = 0; mc < 4; mc++) {
            __syncthreads();
            const float* pw = proj_w + (size_t)mc * 32 * 512;
            for (int i = tid; i < 16384; i += NT) s[OFF_PW + i] = pw[i];
            __syncthreads();
            #pragma unroll
            for (int rr = 0; rr < 2; rr++) {
                int mloc = wrp + rr * 16;
                int m = mc * 32 + mloc;
                const float* ar  = s + OFF_ATT + lane * 513;
                const float* wr2 = s + OFF_PW + mloc * 512;
                float a0 = 0.f, a1 = 0.f;
                #pragma unroll 8
                for (int j = 0; j < 512; j += 2) {
                    a0 += ar[j]     * wr2[j];
                    a1 += ar[j + 1] * wr2[j + 1];
                }
                s[OFF_Y + lane * 129 + m] = a0 + a1 + __ldg(&proj_b[m]);
            }
        }
    }

    // ================= Phase 4: final conv (32->64, kw=13) + residual =================
    {
        __syncthreads();
        for (int i = tid; i < 26624; i += NT) s[OFF_FCW + i] = fc_w[i];
        __syncthreads();
        const int l = tid & 127;
        const int cobase = (tid >> 7) * 16;
        float acc[16];
        #pragma unroll
        for (int i = 0; i < 16; i++) acc[i] = __ldg(&fc_b[cobase + i]);
        for (int ci = 0; ci < 32; ci++) {
            const float* yr = s + OFF_Y + ci * 129 + l - 6;
            const float* wr = s + OFF_FCW + (cobase * 32 + ci) * 13;
            #pragma unroll
            for (int kk = 0; kk < 13; kk++) {
                int pos = l + kk - 6;
                float xv = ((unsigned)pos < 128u) ? yr[kk] : 0.f;
                #pragma unroll
                for (int i = 0; i < 16; i++)
                    acc[i] += xv * wr[kk + i * 416];   // (co+i)*32*13 stride
            }
        }
        const float* qres = gq + boff;
        #pragma unroll
        for (int i = 0; i < 16; i++)
            s[OFF_Z + (cobase + i) * 128 + l] = acc[i] + qres[(cobase + i) * 128 + l];
    }

    // ================= Phase 5: LayerNorm over last dim (unbiased std, /(sigma+eps)) =================
    {
        __syncthreads();
        const int lane = tid & 31;
        const int wrp  = tid >> 5;
        #pragma unroll
        for (int it = 0; it < 4; it++) {
            int r = wrp + it * 16;
            const float* zr = s + OFF_Z + r * 128;
            float v0 = zr[lane], v1 = zr[lane + 32], v2 = zr[lane + 64], v3 = zr[lane + 96];
            float sm = v0 + v1 + v2 + v3;
            #pragma unroll
            for (int o = 16; o > 0; o >>= 1) sm += __shfl_xor_sync(0xffffffffu, sm, o);
            float mu = sm * (1.f / 128.f);
            float d0 = v0 - mu, d1 = v1 - mu, d2 = v2 - mu, d3 = v3 - mu;
            float s2 = d0 * d0 + d1 * d1 + d2 * d2 + d3 * d3;
            #pragma unroll
            for (int o = 16; o > 0; o >>= 1) s2 += __shfl_xor_sync(0xffffffffu, s2, o);
            float sigma = sqrtf(s2 * (1.f / 127.f));
            float inv = 1.f / (sigma + 1e-3f);
            float* orow = out + boff + r * 128;
            orow[lane]      = d0 * inv * __ldg(&ln_a[lane])      + __ldg(&ln_b[lane]);
            orow[lane + 32] = d1 * inv * __ldg(&ln_a[lane + 32]) + __ldg(&ln_b[lane + 32]);
            orow[lane + 64] = d2 * inv * __ldg(&ln_a[lane + 64]) + __ldg(&ln_b[lane + 64]);
            orow[lane + 96] = d3 * inv * __ldg(&ln_a[lane + 96]) + __ldg(&ln_b[lane + 96]);
        }
    }
}

extern "C" void kernel_launch(void* const* d_in, const int* in_sizes, int n_in,
                              void* d_out, int out_size)
{
    const float* q      = (const float*)d_in[0];
    const float* k      = (const float*)d_in[1];
    const float* v      = (const float*)d_in[2];
    const float* cq_w   = (const float*)d_in[3];
    const float* cq_b   = (const float*)d_in[4];
    const float* ck_w   = (const float*)d_in[5];
    const float* ck_b   = (const float*)d_in[6];
    const float* cv_w   = (const float*)d_in[7];
    const float* cv_b   = (const float*)d_in[8];
    const float* w_qs   = (const float*)d_in[9];
    const float* w_ks   = (const float*)d_in[10];
    const float* w_vs   = (const float*)d_in[11];
    const float* proj_w = (const float*)d_in[12];
    const float* proj_b = (const float*)d_in[13];
    const float* fc_w   = (const float*)d_in[14];
    const float* fc_b   = (const float*)d_in[15];
    const float* ln_a   = (const float*)d_in[16];
    const float* ln_b   = (const float*)d_in[17];
    float* outp = (float*)d_out;

    const int B = in_sizes[0] / (64 * 128);

    cudaFuncSetAttribute(ha_kernel, cudaFuncAttributeMaxDynamicSharedMemorySize, SMEM_BYTES);
    ha_kernel<<<B, NT, SMEM_BYTES>>>(q, k, v, cq_w, cq_b, ck_w, ck_b, cv_w, cv_b,
                                     w_qs, w_ks, w_vs, proj_w, proj_b, fc_w, fc_b,
                                     ln_a, ln_b, outp);
}

// round 3
// speedup vs baseline: 1.0005x; 1.0005x over previous
#include <cuda_runtime.h>

// Problem constants
// B=2048, DKV=64, L=128, H=16, DT=32, KW=13, PAD=6
#define NT 512
#define SMEM_FLOATS 47872
#define SMEM_BYTES (SMEM_FLOATS * 4)

// shared-memory layout offsets (floats)
#define OFF_QB   0        // 4096   (reused as Y in phase 3: 32*129=4128)
#define OFF_KB   4096
#define OFF_VB   8192
#define OFF_ATT  12288    // 32*513 = 16416 -> ends 28704
#define OFF_IN   12288    // phase1: 64*140 = 8960 -> ends 21248 (overlays ATT, dead then)
#define OFF_CW   21248    // 26624 -> ends 47872
#define OFF_WH   28704    // 3*4096 = 12288 -> ends 40992
#define OFF_QH   40992    // 32*33 = 1056
#define OFF_KH   42048
#define OFF_VH   43104
#define OFF_SC   44160    // 1024 -> 45184
#define OFF_Y    0        // 32*129 = 4128
#define OFF_PW   28704    // 16384 -> 45088
#define OFF_FCW  4160     // 26624 -> 30784
#define OFF_Z    30784    // 8192 -> 38976

__global__ void __launch_bounds__(NT, 1)
ha_kernel(const float* __restrict__ gq, const float* __restrict__ gk, const float* __restrict__ gv,
          const float* __restrict__ cq_w, const float* __restrict__ cq_b,
          const float* __restrict__ ck_w, const float* __restrict__ ck_b,
          const float* __restrict__ cv_w, const float* __restrict__ cv_b,
          const float* __restrict__ w_qs, const float* __restrict__ w_ks, const float* __restrict__ w_vs,
          const float* __restrict__ proj_w, const float* __restrict__ proj_b,
          const float* __restrict__ fc_w, const float* __restrict__ fc_b,
          const float* __restrict__ ln_a, const float* __restrict__ ln_b,
          float* __restrict__ out)
{
    extern __shared__ float s[];
    const int tid = threadIdx.x;
    const int b = blockIdx.x;
    const size_t boff = (size_t)b * 8192;   // 64*128

    // ================= Phase 1: conv1d(q/k/v): (64,128) -> (32,128), kw=13, pad=6 =================
    {
        const int l = tid & 127;
        const int cobase = (tid >> 7) * 8;   // quarter -> 8 output channels each
        for (int m = 0; m < 3; m++) {
            const float* xin = (m == 0 ? gq : m == 1 ? gk : gv) + boff;
            const float* cw  = (m == 0 ? cq_w : m == 1 ? ck_w : cv_w);
            const float* cb  = (m == 0 ? cq_b : m == 1 ? ck_b : cv_b);
            float* dst = s + (m == 0 ? OFF_QB : m == 1 ? OFF_KB : OFF_VB);
            __syncthreads();
            // zero the 6-element pads of each 140-wide row
            for (int i = tid; i < 64 * 12; i += NT) {
                int ci = i / 12, j = i % 12;
                s[OFF_IN + ci * 140 + (j < 6 ? j : j + 128)] = 0.f;
            }
            // fill input rows (coalesced)
            for (int i = tid; i < 8192; i += NT)
                s[OFF_IN + (i >> 7) * 140 + 6 + (i & 127)] = xin[i];
            // conv weights 32*64*13
            for (int i = tid; i < 26624; i += NT) s[OFF_CW + i] = cw[i];
            __syncthreads();

            float acc[8];
            #pragma unroll
            for (int i = 0; i < 8; i++) acc[i] = __ldg(&cb[cobase + i]);
            for (int ci = 0; ci < 64; ci++) {
                const float* ir = s + OFF_IN + ci * 140 + l;          // ir[kk] = in[ci][l+kk-6]
                const float* wr = s + OFF_CW + (cobase * 64 + ci) * 13;
                #pragma unroll
                for (int kk = 0; kk < 13; kk++) {
                    float xv = ir[kk];
                    #pragma unroll
                    for (int i = 0; i < 8; i++)
                        acc[i] += xv * wr[kk + i * 832];               // (co+i)*64*13 stride
                }
            }
            #pragma unroll
            for (int i = 0; i < 8; i++) dst[(cobase + i) * 128 + l] = acc[i];
        }
    }

    // ================= Phase 2: per-head projections + attention =================
    {
        const int lane = tid & 31;
        const int wrp  = tid >> 5;   // 0..15
        const float inv_t = 0.08838834764831845f;   // 1/sqrt(128)
        for (int h = 0; h < 16; h++) {
            __syncthreads();
            const float* wq = w_qs + h * 4096;
            const float* wk = w_ks + h * 4096;
            const float* wv = w_vs + h * 4096;
            for (int i = tid; i < 4096; i += NT) {
                s[OFF_WH + i]        = wq[i];
                s[OFF_WH + 4096 + i] = wk[i];
                s[OFF_WH + 8192 + i] = wv[i];
            }
            __syncthreads();
            // qh/kh/vh: [32,32] each; qh[t][d] = sum_l qb[t][l] * w[l][d]
            #pragma unroll
            for (int m = 0; m < 3; m++) {
                const float* src = s + (m == 0 ? OFF_QB : m == 1 ? OFF_KB : OFF_VB);
                const float* W   = s + OFF_WH + m * 4096;
                float* dst       = s + (m == 0 ? OFF_QH : m == 1 ? OFF_KH : OFF_VH);
                #pragma unroll
                for (int rr = 0; rr < 2; rr++) {
                    int tt = wrp + rr * 16;
                    const float* sr = src + tt * 128;
                    float a0 = 0.f, a1 = 0.f;
                    #pragma unroll 8
                    for (int l2 = 0; l2 < 128; l2 += 2) {
                        a0 += sr[l2]     * W[l2 * 32 + lane];
                        a1 += sr[l2 + 1] * W[(l2 + 1) * 32 + lane];
                    }
                    dst[tt * 33 + lane] = a0 + a1;   // stride 33: conflict-free transposed reads
                }
            }
            __syncthreads();
            // scores[q][k] = dot(qh[q], kh[k]) / sqrt(128)
            #pragma unroll
            for (int rr = 0; rr < 2; rr++) {
                int qq = wrp + rr * 16;
                float a = 0.f;
                #pragma unroll
                for (int d = 0; d < 32; d++)
                    a += s[OFF_QH + qq * 33 + d] * s[OFF_KH + lane * 33 + d];
                s[OFF_SC + qq * 32 + lane] = a * inv_t;
            }
            __syncthreads();
            // softmax over k (rows handled one-per-warp)
            #pragma unroll
            for (int rr = 0; rr < 2; rr++) {
                int r = wrp + rr * 16;
                float x = s[OFF_SC + r * 32 + lane];
                float mx = x;
                #pragma unroll
                for (int o = 16; o > 0; o >>= 1)
                    mx = fmaxf(mx, __shfl_xor_sync(0xffffffffu, mx, o));
                float e = __expf(x - mx);
                float sum = e;
                #pragma unroll
                for (int o = 16; o > 0; o >>= 1)
                    sum += __shfl_xor_sync(0xffffffffu, sum, o);
                s[OFF_SC + r * 32 + lane] = e / sum;
            }
            __syncthreads();
            // out = attn @ vh -> att_cat[t][h*32+d]  (row stride 513: conflict-free in proj)
            #pragma unroll
            for (int rr = 0; rr < 2; rr++) {
                int tt = wrp + rr * 16;
                float a = 0.f;
                #pragma unroll
                for (int kk = 0; kk < 32; kk++)
                    a += s[OFF_SC + tt * 32 + kk] * s[OFF_VH + kk * 33 + lane];
                s[OFF_ATT + tt * 513 + h * 32 + lane] = a;
            }
        }
    }

    // ================= Phase 3: proj  y[t][m] = att[t][:512] . proj_w[m][:512] + b[m] =================
    {
        const int lane = tid & 31;
        const int wrp  = tid >> 5;
        for (int mc = 0; mc < 4; mc++) {
            __syncthreads();
            const float* pw = proj_w + (size_t)mc * 32 * 512;
            for (int i = tid; i < 16384; i += NT) s[OFF_PW + i] = pw[i];
            __syncthreads();
            #pragma unroll
            for (int rr = 0; rr < 2; rr++) {
                int mloc = wrp + rr * 16;
                int m = mc * 32 + mloc;
                const float* ar  = s + OFF_ATT + lane * 513;
                const float* wr2 = s + OFF_PW + mloc * 512;
                float a0 = 0.f, a1 = 0.f;
                #pragma unroll 8
                for (int j = 0; j < 512; j += 2) {
                    a0 += ar[j]     * wr2[j];
                    a1 += ar[j + 1] * wr2[j + 1];
                }
                s[OFF_Y + lane * 129 + m] = a0 + a1 + __ldg(&proj_b[m]);
            }
        }
    }

    // ================= Phase 4: final conv (32->64, kw=13) + residual =================
    {
        __syncthreads();
        for (int i = tid; i < 26624; i += NT) s[OFF_FCW + i] = fc_w[i];
        __syncthreads();
        const int l = tid & 127;
        const int cobase = (tid >> 7) * 16;
        float acc[16];
        #pragma unroll
        for (int i = 0; i < 16; i++) acc[i] = __ldg(&fc_b[cobase + i]);
        for (int ci = 0; ci < 32; ci++) {
            const float* yr = s + OFF_Y + ci * 129 + l - 6;
            const float* wr = s + OFF_FCW + (cobase * 32 + ci) * 13;
            #pragma unroll
            for (int kk = 0; kk < 13; kk++) {
                int pos = l + kk - 6;
                float xv = ((unsigned)pos < 128u) ? yr[kk] : 0.f;
                #pragma unroll
                for (int i = 0; i < 16; i++)
                    acc[i] += xv * wr[kk + i * 416];   // (co+i)*32*13 stride
            }
        }
        const float* qres = gq + boff;
        #pragma unroll
        for (int i = 0; i < 16; i++)
            s[OFF_Z + (cobase + i) * 128 + l] = acc[i] + qres[(cobase + i) * 128 + l];
    }

    // ================= Phase 5: LayerNorm over last dim (unbiased std, /(sigma+eps)) =================
    {
        __syncthreads();
        const int lane = tid & 31;
        const int wrp  = tid >> 5;
        #pragma unroll
        for (int it = 0; it < 4; it++) {
            int r = wrp + it * 16;
            const float* zr = s + OFF_Z + r * 128;
            float v0 = zr[lane], v1 = zr[lane + 32], v2 = zr[lane + 64], v3 = zr[lane + 96];
            float sm = v0 + v1 + v2 + v3;
            #pragma unroll
            for (int o = 16; o > 0; o >>= 1) sm += __shfl_xor_sync(0xffffffffu, sm, o);
            float mu = sm * (1.f / 128.f);
            float d0 = v0 - mu, d1 = v1 - mu, d2 = v2 - mu, d3 = v3 - mu;
            float s2 = d0 * d0 + d1 * d1 + d2 * d2 + d3 * d3;
            #pragma unroll
            for (int o = 16; o > 0; o >>= 1) s2 += __shfl_xor_sync(0xffffffffu, s2, o);
            float sigma = sqrtf(s2 * (1.f / 127.f));
            float inv = 1.f / (sigma + 1e-3f);
            float* orow = out + boff + r * 128;
            orow[lane]      = d0 * inv * __ldg(&ln_a[lane])      + __ldg(&ln_b[lane]);
            orow[lane + 32] = d1 * inv * __ldg(&ln_a[lane + 32]) + __ldg(&ln_b[lane + 32]);
            orow[lane + 64] = d2 * inv * __ldg(&ln_a[lane + 64]) + __ldg(&ln_b[lane + 64]);
            orow[lane + 96] = d3 * inv * __ldg(&ln_a[lane + 96]) + __ldg(&ln_b[lane + 96]);
        }
    }
}

extern "C" void kernel_launch(void* const* d_in, const int* in_sizes, int n_in,
                              void* d_out, int out_size)
{
    const float* q      = (const float*)d_in[0];
    const float* k      = (const float*)d_in[1];
    const float* v      = (const float*)d_in[2];
    const float* cq_w   = (const float*)d_in[3];
    const float* cq_b   = (const float*)d_in[4];
    const float* ck_w   = (const float*)d_in[5];
    const float* ck_b   = (const float*)d_in[6];
    const float* cv_w   = (const float*)d_in[7];
    const float* cv_b   = (const float*)d_in[8];
    const float* w_qs   = (const float*)d_in[9];
    const float* w_ks   = (const float*)d_in[10];
    const float* w_vs   = (const float*)d_in[11];
    const float* proj_w = (const float*)d_in[12];
    const float* proj_b = (const float*)d_in[13];
    const float* fc_w   = (const float*)d_in[14];
    const float* fc_b   = (const float*)d_in[15];
    const float* ln_a   = (const float*)d_in[16];
    const float* ln_b   = (const float*)d_in[17];
    float* outp = (float*)d_out;

    const int B = in_sizes[0] / (64 * 128);

    cudaFuncSetAttribute(ha_kernel, cudaFuncAttributeMaxDynamicSharedMemorySize, SMEM_BYTES);
    ha_kernel<<<B, NT, SMEM_BYTES>>>(q, k, v, cq_w, cq_b, ck_w, ck_b, cv_w, cv_b,
                                     w_qs, w_ks, w_vs, proj_w, proj_b, fc_w, fc_b,
                                     ln_a, ln_b, outp);
}

// round 4
// speedup vs baseline: 1.9774x; 1.9763x over previous
#include <cuda_runtime.h>

// B=2048, DKV=64, L=128, H=16, DT=32, KW=13, PAD=6
#define NT 512
#define QS 132     // qb/kb/vb row stride (pad for conflict-free strided reads)
#define SCS 33     // qh/kh/vh scratch row stride
#define ATS 516    // att row stride (mult of 4, bank offset 4)

// shared layout (floats)
#define OFF_QKV 0            // 3 * 32*132 = 12672          [P1 out, P2 A]
#define OFF_IN  12672        // 64*140 = 8960               [P1 only]
#define OFF_CW  21632        // 26624 -> 48256              [P1 only]
#define OFF_SCR 12672        // 8 heads * 3 * 32*33 = 25344 [P2 only]
#define OFF_ATT 38016        // 32*516 = 16512              [P2 -> P3]
#define OFF_Y   0            // 32*140 = 4480               [P3 -> P4]
#define OFF_FCW 4480         // 26624 -> 31104              [P4]
#define OFF_Z   31104        // 8192 -> 39296               [P4 -> P5]
#define SMEM_FLOATS 54528
#define SMEM_BYTES (SMEM_FLOATS * 4)

// One warp computes C(32x32) = A(32x128) @ B(128x32); A in smem (stride QS),
// B streamed from gmem/L2 with distance-1 float4 prefetch, C to smem (stride SCS).
// TN=4: full 32 rows (tbase=0). TN=2: 16-row half (tbase 0 or 16).
template<int TN>
__device__ __forceinline__ void gemm32(const float* __restrict__ A,
                                       const float* __restrict__ Bg,
                                       float* __restrict__ C,
                                       int tbase, int tr, int dc)
{
    float acc[TN][8];
#pragma unroll
    for (int i = 0; i < TN; i++)
#pragma unroll
        for (int j = 0; j < 8; j++) acc[i][j] = 0.f;

    const float* bp = Bg + dc * 8;
    float4 b0 = __ldg((const float4*)bp);
    float4 b1 = __ldg((const float4*)(bp + 4));
#pragma unroll 2
    for (int l = 0; l < 128; l++) {
        const int lp = (l < 127) ? l + 1 : 127;   // clamp: no OOB prefetch
        float4 n0 = __ldg((const float4*)(bp + lp * 32));
        float4 n1 = __ldg((const float4*)(bp + lp * 32 + 4));
        float a[TN];
#pragma unroll
        for (int i = 0; i < TN; i++) a[i] = A[(tbase + tr + 8 * i) * QS + l];
        float bb[8] = {b0.x, b0.y, b0.z, b0.w, b1.x, b1.y, b1.z, b1.w};
#pragma unroll
        for (int i = 0; i < TN; i++)
#pragma unroll
            for (int j = 0; j < 8; j++)
                acc[i][j] = fmaf(a[i], bb[j], acc[i][j]);
        b0 = n0; b1 = n1;
    }
#pragma unroll
    for (int i = 0; i < TN; i++)
#pragma unroll
        for (int j = 0; j < 8; j++)
            C[(tbase + tr + 8 * i) * SCS + dc * 8 + j] = acc[i][j];
}

__global__ void __launch_bounds__(NT, 1)
ha_kernel(const float* __restrict__ gq, const float* __restrict__ gk, const float* __restrict__ gv,
          const float* __restrict__ cq_w, const float* __restrict__ cq_b,
          const float* __restrict__ ck_w, const float* __restrict__ ck_b,
          const float* __restrict__ cv_w, const float* __restrict__ cv_b,
          const float* __restrict__ w_qs, const float* __restrict__ w_ks, const float* __restrict__ w_vs,
          const float* __restrict__ proj_w, const float* __restrict__ proj_b,
          const float* __restrict__ fc_w, const float* __restrict__ fc_b,
          const float* __restrict__ ln_a, const float* __restrict__ ln_b,
          float* __restrict__ out)
{
    extern __shared__ float s[];
    const int tid  = threadIdx.x;
    const int w    = tid >> 5;
    const int lane = tid & 31;
    const size_t boff = (size_t)blockIdx.x * 8192;   // 64*128

    // ============ Phase 1: conv1d q/k/v (64->32, kw13, pad6) ============
    {
        const int lg = lane & 15, cs = lane >> 4;
        const int l0 = lg * 8;
        const int co = w * 2 + cs;                   // 16 warps * 2 = 32 co
#pragma unroll 1
        for (int m = 0; m < 3; m++) {
            const float* xin = (m == 0 ? gq : m == 1 ? gk : gv) + boff;
            const float* cw  = (m == 0 ? cq_w : m == 1 ? ck_w : cv_w);
            const float* cb  = (m == 0 ? cq_b : m == 1 ? ck_b : cv_b);
            float* dst = s + OFF_QKV + m * 4224;
            __syncthreads();
            for (int i = tid; i < 64 * 12; i += NT) {
                int ci = i / 12, j = i % 12;
                s[OFF_IN + ci * 140 + (j < 6 ? j : j + 128)] = 0.f;
            }
            for (int i = tid; i < 8192; i += NT)
                s[OFF_IN + (i >> 7) * 140 + 6 + (i & 127)] = xin[i];
            for (int i = tid; i < 26624; i += NT) s[OFF_CW + i] = cw[i];
            __syncthreads();

            float acc[8];
            {
                float bv = __ldg(&cb[co]);
#pragma unroll
                for (int i = 0; i < 8; i++) acc[i] = bv;
            }
#pragma unroll 1
            for (int ci = 0; ci < 64; ci++) {
                const float* xp = s + OFF_IN + ci * 140 + l0;  // aligned: 140%4==0, l0%8==0
                float xw[20];
#pragma unroll
                for (int q4 = 0; q4 < 5; q4++) {
                    float4 t4 = *(const float4*)(xp + q4 * 4);
                    xw[q4 * 4 + 0] = t4.x; xw[q4 * 4 + 1] = t4.y;
                    xw[q4 * 4 + 2] = t4.z; xw[q4 * 4 + 3] = t4.w;
                }
                const float* wr = s + OFF_CW + (co * 64 + ci) * 13;
#pragma unroll
                for (int kk = 0; kk < 13; kk++) {
                    float wv = wr[kk];
#pragma unroll
                    for (int dl = 0; dl < 8; dl++)
                        acc[dl] = fmaf(xw[kk + dl], wv, acc[dl]);
                }
            }
            *(float4*)(dst + co * QS + l0)     = make_float4(acc[0], acc[1], acc[2], acc[3]);
            *(float4*)(dst + co * QS + l0 + 4) = make_float4(acc[4], acc[5], acc[6], acc[7]);
        }
    }

    // ============ Phase 2: per-head projections + attention, 2 passes of 8 heads ============
    {
        const int dc = lane & 3, tr = lane >> 2;
        const float inv_t = 0.08838834764831845f;   // 1/sqrt(128)
#pragma unroll 1
        for (int p = 0; p < 2; p++) {
            __syncthreads();   // SCR reuse / P1 done
            // full GEMM: g = w -> (h_local, m)
            {
                const int g = w, hl = g / 3, m = g % 3;
                const float* Bsrc = (m == 0 ? w_qs : m == 1 ? w_ks : w_vs) + (p * 8 + hl) * 4096;
                gemm32<4>(s + OFF_QKV + m * 4224, Bsrc,
                          s + OFF_SCR + hl * 3168 + m * 1056, 0, tr, dc);
            }
            // half GEMM: g = 16 + w/2, rows half = (w&1)*16
            {
                const int g = 16 + (w >> 1), hl = g / 3, m = g % 3;
                const float* Bsrc = (m == 0 ? w_qs : m == 1 ? w_ks : w_vs) + (p * 8 + hl) * 4096;
                gemm32<2>(s + OFF_QKV + m * 4224, Bsrc,
                          s + OFF_SCR + hl * 3168 + m * 1056, (w & 1) * 16, tr, dc);
            }
            __syncthreads();
            // attention: 2 warps per head (q-halves)
            {
                const int hl = w >> 1, qbase = (w & 1) * 16;
                float* qh = s + OFF_SCR + hl * 3168;
                float* kh = qh + 1056;
                float* vh = qh + 2112;
                float sc[2][8];
#pragma unroll
                for (int i = 0; i < 2; i++)
#pragma unroll
                    for (int j = 0; j < 8; j++) sc[i][j] = 0.f;
#pragma unroll 4
                for (int d = 0; d < 32; d++) {
                    float a0 = qh[(qbase + tr) * SCS + d];
                    float a1 = qh[(qbase + tr + 8) * SCS + d];
#pragma unroll
                    for (int j = 0; j < 8; j++) {
                        float bv = kh[(dc * 8 + j) * SCS + d];
                        sc[0][j] = fmaf(a0, bv, sc[0][j]);
                        sc[1][j] = fmaf(a1, bv, sc[1][j]);
                    }
                }
                // softmax along k (row = 4 dc lanes x 8 regs)
#pragma unroll
                for (int i = 0; i < 2; i++) {
                    float mx = -1e30f;
#pragma unroll
                    for (int j = 0; j < 8; j++) { sc[i][j] *= inv_t; mx = fmaxf(mx, sc[i][j]); }
                    mx = fmaxf(mx, __shfl_xor_sync(0xffffffffu, mx, 1));
                    mx = fmaxf(mx, __shfl_xor_sync(0xffffffffu, mx, 2));
                    float sum = 0.f;
#pragma unroll
                    for (int j = 0; j < 8; j++) { sc[i][j] = __expf(sc[i][j] - mx); sum += sc[i][j]; }
                    sum += __shfl_xor_sync(0xffffffffu, sum, 1);
                    sum += __shfl_xor_sync(0xffffffffu, sum, 2);
                    float inv = 1.f / sum;
#pragma unroll
                    for (int j = 0; j < 8; j++) sc[i][j] *= inv;
                }
                // attn -> qh slot (qh dead)
#pragma unroll
                for (int i = 0; i < 2; i++)
#pragma unroll
                    for (int j = 0; j < 8; j++)
                        qh[(qbase + tr + 8 * i) * SCS + dc * 8 + j] = sc[i][j];
                __syncwarp();
                // AV
                float av[2][8];
#pragma unroll
                for (int i = 0; i < 2; i++)
#pragma unroll
                    for (int j = 0; j < 8; j++) av[i][j] = 0.f;
#pragma unroll 4
                for (int k2 = 0; k2 < 32; k2++) {
                    float a0 = qh[(qbase + tr) * SCS + k2];
                    float a1 = qh[(qbase + tr + 8) * SCS + k2];
#pragma unroll
                    for (int j = 0; j < 8; j++) {
                        float bv = vh[k2 * SCS + dc * 8 + j];
                        av[0][j] = fmaf(a0, bv, av[0][j]);
                        av[1][j] = fmaf(a1, bv, av[1][j]);
                    }
                }
                const int h = p * 8 + hl;
#pragma unroll
                for (int i = 0; i < 2; i++)
#pragma unroll
                    for (int j = 0; j < 8; j++)
                        s[OFF_ATT + (qbase + tr + 8 * i) * ATS + h * 32 + dc * 8 + j] = av[i][j];
            }
        }
    }

    // zero Y pads (Y region = old QKV, no longer read)
    for (int i = tid; i < 32 * 12; i += NT) {
        int t = i / 12, j = i % 12;
        s[OFF_Y + t * 140 + (j < 6 ? j : j + 128)] = 0.f;
    }
    __syncthreads();   // ATT complete

    // ============ Phase 3: stage FCW (for P4) + proj y[t][m] ============
    for (int i = tid; i < 26624; i += NT) s[OFF_FCW + i] = fc_w[i];
    {
        const int dc = lane & 3, tr = lane >> 2;
        const int m0 = w * 8 + dc * 2;               // this thread: m0, m0+1
        const float* pw0 = proj_w + (size_t)m0 * 512;
        const float* pw1 = pw0 + 512;
        float4 c0 = __ldg((const float4*)pw0);
        float4 c1 = __ldg((const float4*)pw1);
        float acc[4][2];
#pragma unroll
        for (int i = 0; i < 4; i++) { acc[i][0] = 0.f; acc[i][1] = 0.f; }
#pragma unroll 2
        for (int jq = 0; jq < 128; jq++) {
            const int jn = (jq < 127) ? jq + 1 : 127;
            float4 n0 = __ldg((const float4*)(pw0 + jn * 4));
            float4 n1 = __ldg((const float4*)(pw1 + jn * 4));
#pragma unroll
            for (int i = 0; i < 4; i++) {
                float4 a4 = *(const float4*)(s + OFF_ATT + (tr + 8 * i) * ATS + jq * 4);
                acc[i][0] = fmaf(a4.x, c0.x, fmaf(a4.y, c0.y, fmaf(a4.z, c0.z, fmaf(a4.w, c0.w, acc[i][0]))));
                acc[i][1] = fmaf(a4.x, c1.x, fmaf(a4.y, c1.y, fmaf(a4.z, c1.z, fmaf(a4.w, c1.w, acc[i][1]))));
            }
            c0 = n0; c1 = n1;
        }
        const float bb0 = __ldg(&proj_b[m0]);
        const float bb1 = __ldg(&proj_b[m0 + 1]);
#pragma unroll
        for (int i = 0; i < 4; i++) {
            s[OFF_Y + (tr + 8 * i) * 140 + 6 + m0]     = acc[i][0] + bb0;
            s[OFF_Y + (tr + 8 * i) * 140 + 6 + m0 + 1] = acc[i][1] + bb1;
        }
    }
    __syncthreads();

    // ============ Phase 4: final conv (32->64, kw13) + residual ============
    {
        const int lg = lane & 15, cs = lane >> 4;
        const int l0 = lg * 8;
        const int co = w * 4 + cs * 2;               // this thread: co, co+1
        float acc[2][8];
        {
            float b0 = __ldg(&fc_b[co]), b1 = __ldg(&fc_b[co + 1]);
#pragma unroll
            for (int i = 0; i < 8; i++) { acc[0][i] = b0; acc[1][i] = b1; }
        }
#pragma unroll 1
        for (int ci = 0; ci < 32; ci++) {
            const float* xp = s + OFF_Y + ci * 140 + l0;
            float xw[20];
#pragma unroll
            for (int q4 = 0; q4 < 5; q4++) {
                float4 t4 = *(const float4*)(xp + q4 * 4);
                xw[q4 * 4 + 0] = t4.x; xw[q4 * 4 + 1] = t4.y;
                xw[q4 * 4 + 2] = t4.z; xw[q4 * 4 + 3] = t4.w;
            }
            const float* wr0 = s + OFF_FCW + (co * 32 + ci) * 13;
            const float* wr1 = wr0 + 416;
#pragma unroll
            for (int kk = 0; kk < 13; kk++) {
                float w0 = wr0[kk], w1 = wr1[kk];
#pragma unroll
                for (int dl = 0; dl < 8; dl++) {
                    acc[0][dl] = fmaf(xw[kk + dl], w0, acc[0][dl]);
                    acc[1][dl] = fmaf(xw[kk + dl], w1, acc[1][dl]);
                }
            }
        }
        const float* qres = gq + boff;
#pragma unroll
        for (int c2 = 0; c2 < 2; c2++) {
            float4 r0 = __ldg((const float4*)(qres + (co + c2) * 128 + l0));
            float4 r1 = __ldg((const float4*)(qres + (co + c2) * 128 + l0 + 4));
            *(float4*)(s + OFF_Z + (co + c2) * 128 + l0) =
                make_float4(acc[c2][0] + r0.x, acc[c2][1] + r0.y, acc[c2][2] + r0.z, acc[c2][3] + r0.w);
            *(float4*)(s + OFF_Z + (co + c2) * 128 + l0 + 4) =
                make_float4(acc[c2][4] + r1.x, acc[c2][5] + r1.y, acc[c2][6] + r1.z, acc[c2][7] + r1.w);
        }
    }
    __syncthreads();

    // ============ Phase 5: LayerNorm (unbiased std, /(sigma+eps)) ============
    {
#pragma unroll
        for (int it = 0; it < 4; it++) {
            int r = w + it * 16;
            const float* zr = s + OFF_Z + r * 128;
            float v0 = zr[lane], v1 = zr[lane + 32], v2 = zr[lane + 64], v3 = zr[lane + 96];
            float sm = v0 + v1 + v2 + v3;
#pragma unroll
            for (int o = 16; o > 0; o >>= 1) sm += __shfl_xor_sync(0xffffffffu, sm, o);
            float mu = sm * (1.f / 128.f);
            float d0 = v0 - mu, d1 = v1 - mu, d2 = v2 - mu, d3 = v3 - mu;
            float s2 = d0 * d0 + d1 * d1 + d2 * d2 + d3 * d3;
#pragma unroll
            for (int o = 16; o > 0; o >>= 1) s2 += __shfl_xor_sync(0xffffffffu, s2, o);
            float sigma = sqrtf(s2 * (1.f / 127.f));
            float inv = 1.f / (sigma + 1e-3f);
            float* orow = out + boff + r * 128;
            orow[lane]      = d0 * inv * __ldg(&ln_a[lane])      + __ldg(&ln_b[lane]);
            orow[lane + 32] = d1 * inv * __ldg(&ln_a[lane + 32]) + __ldg(&ln_b[lane + 32]);
            orow[lane + 64] = d2 * inv * __ldg(&ln_a[lane + 64]) + __ldg(&ln_b[lane + 64]);
            orow[lane + 96] = d3 * inv * __ldg(&ln_a[lane + 96]) + __ldg(&ln_b[lane + 96]);
        }
    }
}

extern "C" void kernel_launch(void* const* d_in, const int* in_sizes, int n_in,
                              void* d_out, int out_size)
{
    const float* q      = (const float*)d_in[0];
    const float* k      = (const float*)d_in[1];
    const float* v      = (const float*)d_in[2];
    const float* cq_w   = (const float*)d_in[3];
    const float* cq_b   = (const float*)d_in[4];
    const float* ck_w   = (const float*)d_in[5];
    const float* ck_b   = (const float*)d_in[6];
    const float* cv_w   = (const float*)d_in[7];
    const float* cv_b   = (const float*)d_in[8];
    const float* w_qs   = (const float*)d_in[9];
    const float* w_ks   = (const float*)d_in[10];
    const float* w_vs   = (const float*)d_in[11];
    const float* proj_w = (const float*)d_in[12];
    const float* proj_b = (const float*)d_in[13];
    const float* fc_w   = (const float*)d_in[14];
    const float* fc_b   = (const float*)d_in[15];
    const float* ln_a   = (const float*)d_in[16];
    const float* ln_b   = (const float*)d_in[17];
    float* outp = (float*)d_out;

    const int B = in_sizes[0] / (64 * 128);

    cudaFuncSetAttribute(ha_kernel, cudaFuncAttributeMaxDynamicSharedMemorySize, SMEM_BYTES);
    ha_kernel<<<B, NT, SMEM_BYTES>>>(q, k, v, cq_w, cq_b, ck_w, ck_b, cv_w, cv_b,
                                     w_qs, w_ks, w_vs, proj_w, proj_b, fc_w, fc_b,
                                     ln_a, ln_b, outp);
}

// round 6
// speedup vs baseline: 2.0539x; 1.0387x over previous
#include <cuda_runtime.h>

// B=2048, DKV=64, L=128, H=16, DT=32, KW=13, PAD=6
#define NT 512
#define QS 132     // qb/kb/vb row stride
#define SCS 34     // qh/kh/vh scratch row stride (even: 8B-aligned pairs)
#define ATS 516    // att row stride

// shared layout (floats)
#define OFF_QKV 0            // 3 * 32*132 = 12672          [P1 out, P2 A]
#define OFF_IN  12672        // 64*140 = 8960               [P1 only]
#define OFF_CW  21632        // 32*64*14 = 28672 -> 50304   [P1 only, tap-padded]
#define OFF_SCR 12672        // 8 heads * 3 * 32*34 = 26112 [P2 only]
#define OFF_ATT 38784        // 32*516 = 16512 -> 55296     [P2 -> P3]
#define OFF_Y   0            // 32*140 = 4480               [P3 -> P4]
#define OFF_FCW 4480         // 64*32*14 = 28672 -> 33152   [P4, tap-padded]
#define OFF_Z   38784        // 8192 (over dead ATT)        [P4 -> P5]
#define SMEM_FLOATS 55296
#define SMEM_BYTES (SMEM_FLOATS * 4)

typedef unsigned long long u64;

__device__ __forceinline__ u64 pk2(float lo, float hi) {
    u64 r; asm("mov.b64 %0,{%1,%2};" : "=l"(r) : "f"(lo), "f"(hi)); return r;
}
__device__ __forceinline__ u64 dup2(float x) { return pk2(x, x); }
__device__ __forceinline__ void upk2(float& lo, float& hi, u64 v) {
    asm("mov.b64 {%0,%1},%2;" : "=f"(lo), "=f"(hi) : "l"(v));
}
// d = a * b + d, packed fp32x2 (full fp32 precision per lane)
__device__ __forceinline__ void fma2(u64& d, u64 a, u64 b) {
    asm("fma.rn.f32x2 %0,%1,%2,%0;" : "+l"(d) : "l"(a), "l"(b));
}
__device__ __forceinline__ u64 lds64(const float* p) {
    return *reinterpret_cast<const u64*>(p);
}

// One warp: C(32x32) = A(32x128) @ B(128x32); A smem rows (stride QS), B streamed
// from gmem as packed pairs (ulonglong2), C to smem (stride SCS, paired stores).
template<int TN>
__device__ __forceinline__ void gemm32(const float* __restrict__ A,
                                       const float* __restrict__ Bg,
                                       float* __restrict__ C,
                                       int tbase, int tr, int dc)
{
    u64 acc[TN][4];
#pragma unroll
    for (int i = 0; i < TN; i++)
#pragma unroll
        for (int j = 0; j < 4; j++) acc[i][j] = 0ull;
    const float* Ar[TN];
#pragma unroll
    for (int i = 0; i < TN; i++) Ar[i] = A + (tbase + tr + 8 * i) * QS;

    const float* bp = Bg + dc * 8;
    ulonglong2 b0 = __ldg((const ulonglong2*)bp);
    ulonglong2 b1 = __ldg((const ulonglong2*)(bp + 4));
#pragma unroll 2
    for (int l = 0; l < 128; l++) {
        const int lp = (l < 127) ? l + 1 : 127;
        ulonglong2 n0 = __ldg((const ulonglong2*)(bp + lp * 32));
        ulonglong2 n1 = __ldg((const ulonglong2*)(bp + lp * 32 + 4));
#pragma unroll
        for (int i = 0; i < TN; i++) {
            u64 ad = dup2(Ar[i][l]);
            fma2(acc[i][0], ad, b0.x);
            fma2(acc[i][1], ad, b0.y);
            fma2(acc[i][2], ad, b1.x);
            fma2(acc[i][3], ad, b1.y);
        }
        b0 = n0; b1 = n1;
    }
#pragma unroll
    for (int i = 0; i < TN; i++)
#pragma unroll
        for (int j = 0; j < 4; j++)
            *reinterpret_cast<u64*>(C + (tbase + tr + 8 * i) * SCS + dc * 8 + 2 * j) = acc[i][j];
}

__global__ void __launch_bounds__(NT, 1)
ha_kernel(const float* __restrict__ gq, const float* __restrict__ gk, const float* __restrict__ gv,
          const float* __restrict__ cq_w, const float* __restrict__ cq_b,
          const float* __restrict__ ck_w, const float* __restrict__ ck_b,
          const float* __restrict__ cv_w, const float* __restrict__ cv_b,
          const float* __restrict__ w_qs, const float* __restrict__ w_ks, const float* __restrict__ w_vs,
          const float* __restrict__ proj_w, const float* __restrict__ proj_b,
          const float* __restrict__ fc_w, const float* __restrict__ fc_b,
          const float* __restrict__ ln_a, const float* __restrict__ ln_b,
          float* __restrict__ out)
{
    extern __shared__ float s[];
    const int tid  = threadIdx.x;
    const int w    = tid >> 5;
    const int lane = tid & 31;
    const size_t boff = (size_t)blockIdx.x * 8192;   // 64*128

    // ============ Phase 1: conv1d q/k/v (64->32, kw13, pad6), f32x2 over kk-pairs ============
    {
        const int lg = lane & 15, cs = lane >> 4;
        const int l0 = lg * 8;
        const int co = w * 2 + cs;                   // 32 co across 16 warps
#pragma unroll 1
        for (int m = 0; m < 3; m++) {
            const float* xin = (m == 0 ? gq : m == 1 ? gk : gv) + boff;
            const float* cw  = (m == 0 ? cq_w : m == 1 ? ck_w : cv_w);
            const float* cb  = (m == 0 ? cq_b : m == 1 ? ck_b : cv_b);
            float* dst = s + OFF_QKV + m * 4224;
            __syncthreads();
            for (int i = tid; i < 64 * 12; i += NT) {
                int ci = i / 12, j = i % 12;
                s[OFF_IN + ci * 140 + (j < 6 ? j : j + 128)] = 0.f;
            }
            for (int i = tid; i < 8192; i += NT)
                s[OFF_IN + (i >> 7) * 140 + 6 + (i & 127)] = xin[i];
            // stage weights with tap stride 14 (8B-aligned kk-pairs)
            for (int i = tid; i < 26624; i += NT)
                s[OFF_CW + (i / 13) * 14 + (i % 13)] = cw[i];
            __syncthreads();

            u64 acc2[8];
            {
                float bv = __ldg(&cb[co]);
#pragma unroll
                for (int dl = 0; dl < 8; dl++) acc2[dl] = pk2(bv, 0.f);   // bias in EVERY output
            }
#pragma unroll 1
            for (int ci = 0; ci < 64; ci++) {
                const float* xp = s + OFF_IN + ci * 140 + l0;
                float xw[20];
#pragma unroll
                for (int q4 = 0; q4 < 5; q4++) {
                    float4 t4 = *(const float4*)(xp + q4 * 4);
                    xw[q4 * 4 + 0] = t4.x; xw[q4 * 4 + 1] = t4.y;
                    xw[q4 * 4 + 2] = t4.z; xw[q4 * 4 + 3] = t4.w;
                }
                u64 xp2[18];
#pragma unroll
                for (int mi = 0; mi < 18; mi++) xp2[mi] = pk2(xw[mi], xw[mi + 1]);
                const float* wr = s + OFF_CW + (co * 64 + ci) * 14;
#pragma unroll
                for (int kk2 = 0; kk2 < 6; kk2++) {
                    u64 w2 = lds64(wr + 2 * kk2);
#pragma unroll
                    for (int dl = 0; dl < 8; dl++)
                        fma2(acc2[dl], xp2[2 * kk2 + dl], w2);
                }
                u64 w12 = dup2(wr[12]);
#pragma unroll
                for (int dl = 0; dl < 8; dl++)
                    fma2(acc2[dl], pk2(xw[12 + dl], 0.f), w12);
            }
            float v[8];
#pragma unroll
            for (int dl = 0; dl < 8; dl++) { float lo, hi; upk2(lo, hi, acc2[dl]); v[dl] = lo + hi; }
            *(float4*)(dst + co * QS + l0)     = make_float4(v[0], v[1], v[2], v[3]);
            *(float4*)(dst + co * QS + l0 + 4) = make_float4(v[4], v[5], v[6], v[7]);
        }
    }

    // ============ Phase 2: per-head projections + attention, 2 passes of 8 heads ============
    {
        const int dc = lane & 3, tr = lane >> 2;
        const float inv_t = 0.08838834764831845f;   // 1/sqrt(128)
#pragma unroll 1
        for (int p = 0; p < 2; p++) {
            __syncthreads();
            // full GEMM: g = w
            {
                const int g = w, hl = g / 3, m = g % 3;
                const float* Bsrc = (m == 0 ? w_qs : m == 1 ? w_ks : w_vs) + (p * 8 + hl) * 4096;
                gemm32<4>(s + OFF_QKV + m * 4224, Bsrc,
                          s + OFF_SCR + hl * 3264 + m * 1088, 0, tr, dc);
            }
            // half GEMM
            {
                const int g = 16 + (w >> 1), hl = g / 3, m = g % 3;
                const float* Bsrc = (m == 0 ? w_qs : m == 1 ? w_ks : w_vs) + (p * 8 + hl) * 4096;
                gemm32<2>(s + OFF_QKV + m * 4224, Bsrc,
                          s + OFF_SCR + hl * 3264 + m * 1088, (w & 1) * 16, tr, dc);
            }
            __syncthreads();
            // attention: 2 warps per head
            {
                const int hl = w >> 1, qbase = (w & 1) * 16;
                float* qh = s + OFF_SCR + hl * 3264;
                float* kh = qh + 1088;
                float* vh = qh + 2176;
                const float* qr0 = qh + (qbase + tr) * SCS;
                const float* qr1 = qh + (qbase + tr + 8) * SCS;
                // QK^T: f32x2 over reduction-d pairs (both operands contiguous, zero packs)
                u64 sc2[2][8];
#pragma unroll
                for (int i = 0; i < 2; i++)
#pragma unroll
                    for (int j = 0; j < 8; j++) sc2[i][j] = 0ull;
#pragma unroll 4
                for (int d2 = 0; d2 < 16; d2++) {
                    u64 q0 = lds64(qr0 + 2 * d2);
                    u64 q1 = lds64(qr1 + 2 * d2);
#pragma unroll
                    for (int j = 0; j < 8; j++) {
                        u64 kv = lds64(kh + (dc * 8 + j) * SCS + 2 * d2);
                        fma2(sc2[0][j], q0, kv);
                        fma2(sc2[1][j], q1, kv);
                    }
                }
                float sc[2][8];
#pragma unroll
                for (int i = 0; i < 2; i++)
#pragma unroll
                    for (int j = 0; j < 8; j++) {
                        float lo, hi; upk2(lo, hi, sc2[i][j]); sc[i][j] = lo + hi;
                    }
                // softmax along k
#pragma unroll
                for (int i = 0; i < 2; i++) {
                    float mx = -1e30f;
#pragma unroll
                    for (int j = 0; j < 8; j++) { sc[i][j] *= inv_t; mx = fmaxf(mx, sc[i][j]); }
                    mx = fmaxf(mx, __shfl_xor_sync(0xffffffffu, mx, 1));
                    mx = fmaxf(mx, __shfl_xor_sync(0xffffffffu, mx, 2));
                    float sum = 0.f;
#pragma unroll
                    for (int j = 0; j < 8; j++) { sc[i][j] = __expf(sc[i][j] - mx); sum += sc[i][j]; }
                    sum += __shfl_xor_sync(0xffffffffu, sum, 1);
                    sum += __shfl_xor_sync(0xffffffffu, sum, 2);
                    float inv = 1.f / sum;
#pragma unroll
                    for (int j = 0; j < 8; j++) sc[i][j] *= inv;
                }
                // attn -> qh rows (each lane overwrites only its own rows)
#pragma unroll
                for (int i = 0; i < 2; i++)
#pragma unroll
                    for (int j = 0; j < 8; j++)
                        qh[(qbase + tr + 8 * i) * SCS + dc * 8 + j] = sc[i][j];
                __syncwarp();
                // AV: f32x2 over output-d pairs (vh contiguous)
                u64 av2[2][4];
#pragma unroll
                for (int i = 0; i < 2; i++)
#pragma unroll
                    for (int jp = 0; jp < 4; jp++) av2[i][jp] = 0ull;
#pragma unroll 4
                for (int k2 = 0; k2 < 32; k2++) {
                    u64 a0 = dup2(qr0[k2]);
                    u64 a1 = dup2(qr1[k2]);
#pragma unroll
                    for (int jp = 0; jp < 4; jp++) {
                        u64 vv = lds64(vh + k2 * SCS + dc * 8 + 2 * jp);
                        fma2(av2[0][jp], a0, vv);
                        fma2(av2[1][jp], a1, vv);
                    }
                }
                const int h = p * 8 + hl;
#pragma unroll
                for (int i = 0; i < 2; i++)
#pragma unroll
                    for (int jp = 0; jp < 4; jp++)
                        *reinterpret_cast<u64*>(s + OFF_ATT + (qbase + tr + 8 * i) * ATS
                                                + h * 32 + dc * 8 + 2 * jp) = av2[i][jp];
            }
        }
    }

    // zero Y pads (Y region = old QKV, dead)
    for (int i = tid; i < 32 * 12; i += NT) {
        int t = i / 12, j = i % 12;
        s[OFF_Y + t * 140 + (j < 6 ? j : j + 128)] = 0.f;
    }
    __syncthreads();   // ATT complete

    // ============ Phase 3: stage FCW (stride 14) + proj, f32x2 over reduction-j pairs ============
    for (int i = tid; i < 26624; i += NT)
        s[OFF_FCW + (i / 13) * 14 + (i % 13)] = fc_w[i];
    {
        const int dc = lane & 3, tr = lane >> 2;
        const int m0 = w * 8 + dc * 2;
        const float* pw0 = proj_w + (size_t)m0 * 512;
        const float* pw1 = pw0 + 512;
        ulonglong2 c0 = __ldg((const ulonglong2*)pw0);
        ulonglong2 c1 = __ldg((const ulonglong2*)pw1);
        const float* ar[4];
#pragma unroll
        for (int i = 0; i < 4; i++) ar[i] = s + OFF_ATT + (tr + 8 * i) * ATS;
        u64 acc2[4][2];
#pragma unroll
        for (int i = 0; i < 4; i++) { acc2[i][0] = 0ull; acc2[i][1] = 0ull; }
#pragma unroll 2
        for (int jq = 0; jq < 128; jq++) {
            const int jn = (jq < 127) ? jq + 1 : 127;
            ulonglong2 n0 = __ldg((const ulonglong2*)(pw0 + jn * 4));
            ulonglong2 n1 = __ldg((const ulonglong2*)(pw1 + jn * 4));
#pragma unroll
            for (int i = 0; i < 4; i++) {
                u64 aLo = lds64(ar[i] + jq * 4);
                u64 aHi = lds64(ar[i] + jq * 4 + 2);
                fma2(acc2[i][0], aLo, c0.x); fma2(acc2[i][0], aHi, c0.y);
                fma2(acc2[i][1], aLo, c1.x); fma2(acc2[i][1], aHi, c1.y);
            }
            c0 = n0; c1 = n1;
        }
        const float bb0 = __ldg(&proj_b[m0]);
        const float bb1 = __ldg(&proj_b[m0 + 1]);
#pragma unroll
        for (int i = 0; i < 4; i++) {
            float l0v, h0v, l1v, h1v;
            upk2(l0v, h0v, acc2[i][0]);
            upk2(l1v, h1v, acc2[i][1]);
            *reinterpret_cast<u64*>(s + OFF_Y + (tr + 8 * i) * 140 + 6 + m0)
                = pk2(l0v + h0v + bb0, l1v + h1v + bb1);
        }
    }
    __syncthreads();

    // ============ Phase 4: final conv (32->64, kw13) + residual, f32x2 over kk-pairs ============
    {
        const int lg = lane & 15, cs = lane >> 4;
        const int l0 = lg * 8;
        const int co = w * 4 + cs * 2;               // this thread: co, co+1
        u64 acc2[2][8];
#pragma unroll
        for (int c2 = 0; c2 < 2; c2++) {
            float bv = __ldg(&fc_b[co + c2]);
#pragma unroll
            for (int dl = 0; dl < 8; dl++) acc2[c2][dl] = pk2(bv, 0.f);   // bias in EVERY output
        }
#pragma unroll 1
        for (int ci = 0; ci < 32; ci++) {
            const float* xp = s + OFF_Y + ci * 140 + l0;
            float xw[20];
#pragma unroll
            for (int q4 = 0; q4 < 5; q4++) {
                float4 t4 = *(const float4*)(xp + q4 * 4);
                xw[q4 * 4 + 0] = t4.x; xw[q4 * 4 + 1] = t4.y;
                xw[q4 * 4 + 2] = t4.z; xw[q4 * 4 + 3] = t4.w;
            }
            u64 xp2[18];
#pragma unroll
            for (int mi = 0; mi < 18; mi++) xp2[mi] = pk2(xw[mi], xw[mi + 1]);
            u64 xt[8];
#pragma unroll
            for (int dl = 0; dl < 8; dl++) xt[dl] = pk2(xw[12 + dl], 0.f);
#pragma unroll
            for (int c2 = 0; c2 < 2; c2++) {
                const float* wr = s + OFF_FCW + ((co + c2) * 32 + ci) * 14;
#pragma unroll
                for (int kk2 = 0; kk2 < 6; kk2++) {
                    u64 w2 = lds64(wr + 2 * kk2);
#pragma unroll
                    for (int dl = 0; dl < 8; dl++)
                        fma2(acc2[c2][dl], xp2[2 * kk2 + dl], w2);
                }
                u64 w12 = dup2(wr[12]);
#pragma unroll
                for (int dl = 0; dl < 8; dl++)
                    fma2(acc2[c2][dl], xt[dl], w12);
            }
        }
        const float* qres = gq + boff;
#pragma unroll
        for (int c2 = 0; c2 < 2; c2++) {
            float v[8];
#pragma unroll
            for (int dl = 0; dl < 8; dl++) { float lo, hi; upk2(lo, hi, acc2[c2][dl]); v[dl] = lo + hi; }
            float4 r0 = __ldg((const float4*)(qres + (co + c2) * 128 + l0));
            float4 r1 = __ldg((const float4*)(qres + (co + c2) * 128 + l0 + 4));
            *(float4*)(s + OFF_Z + (co + c2) * 128 + l0) =
                make_float4(v[0] + r0.x, v[1] + r0.y, v[2] + r0.z, v[3] + r0.w);
            *(float4*)(s + OFF_Z + (co + c2) * 128 + l0 + 4) =
                make_float4(v[4] + r1.x, v[5] + r1.y, v[6] + r1.z, v[7] + r1.w);
        }
    }
    __syncthreads();

    // ============ Phase 5: LayerNorm (unbiased std, /(sigma+eps)) ============
    {
#pragma unroll
        for (int it = 0; it < 4; it++) {
            int r = w + it * 16;
            const float* zr = s + OFF_Z + r * 128;
            float v0 = zr[lane], v1 = zr[lane + 32], v2 = zr[lane + 64], v3 = zr[lane + 96];
            float sm = v0 + v1 + v2 + v3;
#pragma unroll
            for (int o = 16; o > 0; o >>= 1) sm += __shfl_xor_sync(0xffffffffu, sm, o);
            float mu = sm * (1.f / 128.f);
            float d0 = v0 - mu, d1 = v1 - mu, d2 = v2 - mu, d3 = v3 - mu;
            float s2 = d0 * d0 + d1 * d1 + d2 * d2 + d3 * d3;
#pragma unroll
            for (int o = 16; o > 0; o >>= 1) s2 += __shfl_xor_sync(0xffffffffu, s2, o);
            float sigma = sqrtf(s2 * (1.f / 127.f));
            float inv = 1.f / (sigma + 1e-3f);
            float* orow = out + boff + r * 128;
            orow[lane]      = d0 * inv * __ldg(&ln_a[lane])      + __ldg(&ln_b[lane]);
            orow[lane + 32] = d1 * inv * __ldg(&ln_a[lane + 32]) + __ldg(&ln_b[lane + 32]);
            orow[lane + 64] = d2 * inv * __ldg(&ln_a[lane + 64]) + __ldg(&ln_b[lane + 64]);
            orow[lane + 96] = d3 * inv * __ldg(&ln_a[lane + 96]) + __ldg(&ln_b[lane + 96]);
        }
    }
}

extern "C" void kernel_launch(void* const* d_in, const int* in_sizes, int n_in,
                              void* d_out, int out_size)
{
    const float* q      = (const float*)d_in[0];
    const float* k      = (const float*)d_in[1];
    const float* v      = (const float*)d_in[2];
    const float* cq_w   = (const float*)d_in[3];
    const float* cq_b   = (const float*)d_in[4];
    const float* ck_w   = (const float*)d_in[5];
    const float* ck_b   = (const float*)d_in[6];
    const float* cv_w   = (const float*)d_in[7];
    const float* cv_b   = (const float*)d_in[8];
    const float* w_qs   = (const float*)d_in[9];
    const float* w_ks   = (const float*)d_in[10];
    const float* w_vs   = (const float*)d_in[11];
    const float* proj_w = (const float*)d_in[12];
    const float* proj_b = (const float*)d_in[13];
    const float* fc_w   = (const float*)d_in[14];
    const float* fc_b   = (const float*)d_in[15];
    const float* ln_a   = (const float*)d_in[16];
    const float* ln_b   = (const float*)d_in[17];
    float* outp = (float*)d_out;

    const int B = in_sizes[0] / (64 * 128);

    cudaFuncSetAttribute(ha_kernel, cudaFuncAttributeMaxDynamicSharedMemorySize, SMEM_BYTES);
    ha_kernel<<<B, NT, SMEM_BYTES>>>(q, k, v, cq_w, cq_b, ck_w, ck_b, cv_w, cv_b,
                                     w_qs, w_ks, w_vs, proj_w, proj_b, fc_w, fc_b,
                                     ln_a, ln_b, outp);
}

// round 8
// speedup vs baseline: 2.2890x; 1.1144x over previous
#include <cuda_runtime.h>

// B=2048, DKV=64, L=128, H=16, DT=32, KW=13, PAD=6
#define NT 256
#define QS 132     // qb/kb/vb row stride
#define SCS 34     // qh/kh/vh scratch row stride
#define ATS 516    // att smem row stride

// shared layout (floats), peak 25728 (=102,912B) -> 2 CTAs/SM
#define OFF_QKV 0            // 3*32*132 = 12672            [P1 out, P2 A]
#define OFF_IN  12672        // 64*140 = 8960                [P1]
#define OFF_CW  21632        // 32*8*14 = 3584 -> 25216      [P1 weight chunk]
#define OFF_SCR 12672        // 4 heads*3*32*34 = 13056 -> 25728 [P2]
#define OFF_Y   0            // 32*140 = 4480                [P3 -> P4]
#define OFF_ATT 4480         // 32*516 = 16512 -> 20992      [P3]
#define OFF_FCW 4480         // 64*8*14 = 7168 -> 11648      [P4 chunk, over dead ATT]
#define OFF_Z   11648        // 8192 -> 19840                [P4 -> P5]
#define SMEM_FLOATS 25728
#define SMEM_BYTES (SMEM_FLOATS * 4)

typedef unsigned long long u64;

// gmem scratch (allowed: __device__ globals, no allocation)
__device__ float g_att[2048 * 32 * 512];   // per-batch attention concat
__device__ float g_pwT[512 * 128];         // proj_w transposed: pwT[j][m]

__device__ __forceinline__ u64 pk2(float lo, float hi) {
    u64 r; asm("mov.b64 %0,{%1,%2};" : "=l"(r) : "f"(lo), "f"(hi)); return r;
}
__device__ __forceinline__ u64 dup2(float x) { return pk2(x, x); }
__device__ __forceinline__ void upk2(float& lo, float& hi, u64 v) {
    asm("mov.b64 {%0,%1},%2;" : "=f"(lo), "=f"(hi) : "l"(v));
}
__device__ __forceinline__ void fma2(u64& d, u64 a, u64 b) {
    asm("fma.rn.f32x2 %0,%1,%2,%0;" : "+l"(d) : "l"(a), "l"(b));
}
__device__ __forceinline__ u64 lds64(const float* p) {
    return *reinterpret_cast<const u64*>(p);
}

__global__ void transpose_pw_kernel(const float* __restrict__ pw) {
    int idx = blockIdx.x * 512 + threadIdx.x;   // 65536 total
    int j = idx >> 7, m = idx & 127;
    g_pwT[idx] = pw[m * 512 + j];
}

// One warp: C(32x32) = A(32x128) @ B(128x32); A smem (stride QS, lds64 l-pairs),
// B streamed from gmem (dedup'd lines), C to smem (stride SCS).
template<int TN>
__device__ __forceinline__ void gemm32(const float* __restrict__ A,
                                       const float* __restrict__ Bg,
                                       float* __restrict__ C,
                                       int tbase, int tr, int dc)
{
    u64 acc[TN][4];
#pragma unroll
    for (int i = 0; i < TN; i++)
#pragma unroll
        for (int j = 0; j < 4; j++) acc[i][j] = 0ull;
    const float* Ar[TN];
#pragma unroll
    for (int i = 0; i < TN; i++) Ar[i] = A + (tbase + tr + 8 * i) * QS;

    const float* bp = Bg + dc * 8;
    // B for l-pair {2*l2, 2*l2+1}: cE* (even l), cO* (odd l)
    ulonglong2 cE0 = __ldg((const ulonglong2*)bp);
    ulonglong2 cE1 = __ldg((const ulonglong2*)(bp + 4));
    ulonglong2 cO0 = __ldg((const ulonglong2*)(bp + 32));
    ulonglong2 cO1 = __ldg((const ulonglong2*)(bp + 36));
#pragma unroll 2
    for (int l2 = 0; l2 < 64; l2++) {
        const int nb = (l2 < 63) ? (2 * l2 + 2) : 126;
        ulonglong2 nE0 = __ldg((const ulonglong2*)(bp + nb * 32));
        ulonglong2 nE1 = __ldg((const ulonglong2*)(bp + nb * 32 + 4));
        ulonglong2 nO0 = __ldg((const ulonglong2*)(bp + nb * 32 + 32));
        ulonglong2 nO1 = __ldg((const ulonglong2*)(bp + nb * 32 + 36));
#pragma unroll
        for (int i = 0; i < TN; i++) {
            u64 a01 = lds64(Ar[i] + 2 * l2);
            float alo, ahi; upk2(alo, ahi, a01);
            u64 d0 = dup2(alo), d1 = dup2(ahi);
            fma2(acc[i][0], d0, cE0.x); fma2(acc[i][1], d0, cE0.y);
            fma2(acc[i][2], d0, cE1.x); fma2(acc[i][3], d0, cE1.y);
            fma2(acc[i][0], d1, cO0.x); fma2(acc[i][1], d1, cO0.y);
            fma2(acc[i][2], d1, cO1.x); fma2(acc[i][3], d1, cO1.y);
        }
        cE0 = nE0; cE1 = nE1; cO0 = nO0; cO1 = nO1;
    }
#pragma unroll
    for (int i = 0; i < TN; i++)
#pragma unroll
        for (int j = 0; j < 4; j++)
            *reinterpret_cast<u64*>(C + (tbase + tr + 8 * i) * SCS + dc * 8 + 2 * j) = acc[i][j];
}

__global__ void __launch_bounds__(NT, 2)
ha_kernel(const float* __restrict__ gq, const float* __restrict__ gk, const float* __restrict__ gv,
          const float* __restrict__ cq_w, const float* __restrict__ cq_b,
          const float* __restrict__ ck_w, const float* __restrict__ ck_b,
          const float* __restrict__ cv_w, const float* __restrict__ cv_b,
          const float* __restrict__ w_qs, const float* __restrict__ w_ks, const float* __restrict__ w_vs,
          const float* __restrict__ proj_w, const float* __restrict__ proj_b,
          const float* __restrict__ fc_w, const float* __restrict__ fc_b,
          const float* __restrict__ ln_a, const float* __restrict__ ln_b,
          float* __restrict__ out)
{
    extern __shared__ float s[];
    const int tid  = threadIdx.x;
    const int w    = tid >> 5;       // 0..7
    const int lane = tid & 31;
    const size_t boff = (size_t)blockIdx.x * 8192;   // 64*128
    float* gatt = g_att + (size_t)blockIdx.x * 32 * 512;

    // ============ Phase 1: conv1d q/k/v (64->32, kw13, pad6), scalar FFMA ============
    {
        const int co = tid >> 3;          // 0..31
        const int l0 = (tid & 7) * 16;    // 16 outputs per thread
#pragma unroll 1
        for (int m = 0; m < 3; m++) {
            const float* xin = (m == 0 ? gq : m == 1 ? gk : gv) + boff;
            const float* cw  = (m == 0 ? cq_w : m == 1 ? ck_w : cv_w);
            const float* cb  = (m == 0 ? cq_b : m == 1 ? ck_b : cv_b);
            float* dst = s + OFF_QKV + m * 4224;
            __syncthreads();
            for (int i = tid; i < 64 * 12; i += NT) {
                int ci = i / 12, j = i % 12;
                s[OFF_IN + ci * 140 + (j < 6 ? j : j + 128)] = 0.f;
            }
            for (int i = tid; i < 8192; i += NT)
                s[OFF_IN + (i >> 7) * 140 + 6 + (i & 127)] = xin[i];

            float acc[16];
            {
                float bv = __ldg(&cb[co]);
#pragma unroll
                for (int i = 0; i < 16; i++) acc[i] = bv;
            }
#pragma unroll 1
            for (int c = 0; c < 8; c++) {
                const int ci0 = c * 8;
                __syncthreads();
                // stage weight chunk: [co][ci 0..7][kk], tap stride 14
                for (int i = tid; i < 32 * 8 * 13; i += NT) {
                    int coi = i / 104, r = i % 104, ci = r / 13, kk = r % 13;
                    s[OFF_CW + (coi * 8 + ci) * 14 + kk] = cw[(coi * 64 + ci0 + ci) * 13 + kk];
                }
                __syncthreads();
#pragma unroll 1
                for (int ci = 0; ci < 8; ci++) {
                    const float* xp = s + OFF_IN + (ci0 + ci) * 140 + l0;  // xw[0]=x[l0-6]
                    float xw[28];
#pragma unroll
                    for (int q4 = 0; q4 < 7; q4++) {
                        float4 t4 = *(const float4*)(xp + q4 * 4);
                        xw[q4 * 4 + 0] = t4.x; xw[q4 * 4 + 1] = t4.y;
                        xw[q4 * 4 + 2] = t4.z; xw[q4 * 4 + 3] = t4.w;
                    }
                    const float* wr = s + OFF_CW + (co * 8 + ci) * 14;
                    float wk[13];
#pragma unroll
                    for (int t = 0; t < 6; t++) {
                        float lo, hi; upk2(lo, hi, lds64(wr + 2 * t));
                        wk[2 * t] = lo; wk[2 * t + 1] = hi;
                    }
                    wk[12] = wr[12];
#pragma unroll
                    for (int kk = 0; kk < 13; kk++) {
                        float wv = wk[kk];
#pragma unroll
                        for (int i = 0; i < 16; i++)
                            acc[i] = fmaf(xw[i + kk], wv, acc[i]);
                    }
                }
            }
#pragma unroll
            for (int q4 = 0; q4 < 4; q4++)
                *(float4*)(dst + co * QS + l0 + q4 * 4) =
                    make_float4(acc[q4 * 4], acc[q4 * 4 + 1], acc[q4 * 4 + 2], acc[q4 * 4 + 3]);
        }
    }

    // ============ Phase 2: per-head projections + attention, 4 passes of 4 heads ============
    {
        const int dc = lane & 3, tr = lane >> 2;
        const float inv_t = 0.08838834764831845f;   // 1/sqrt(128)
#pragma unroll 1
        for (int p = 0; p < 4; p++) {
            __syncthreads();
            // full gemm: g = w (0..7)
            {
                const int g = w, hl = g / 3, mm = g % 3;
                const float* Bsrc = (mm == 0 ? w_qs : mm == 1 ? w_ks : w_vs) + (p * 4 + hl) * 4096;
                gemm32<4>(s + OFF_QKV + mm * 4224, Bsrc,
                          s + OFF_SCR + hl * 3264 + mm * 1088, 0, tr, dc);
            }
            // half gemm: g = 8 + (w>>1) (8..11)
            {
                const int g = 8 + (w >> 1), hl = g / 3, mm = g % 3;
                const float* Bsrc = (mm == 0 ? w_qs : mm == 1 ? w_ks : w_vs) + (p * 4 + hl) * 4096;
                gemm32<2>(s + OFF_QKV + mm * 4224, Bsrc,
                          s + OFF_SCR + hl * 3264 + mm * 1088, (w & 1) * 16, tr, dc);
            }
            __syncthreads();
            // attention: 2 warps per head (4 heads)
            {
                const int hl = w >> 1, qbase = (w & 1) * 16;
                float* qh = s + OFF_SCR + hl * 3264;
                float* kh = qh + 1088;
                float* vh = qh + 2176;
                const float* qr0 = qh + (qbase + tr) * SCS;
                const float* qr1 = qh + (qbase + tr + 8) * SCS;
                u64 sc2[2][8];
#pragma unroll
                for (int i = 0; i < 2; i++)
#pragma unroll
                    for (int j = 0; j < 8; j++) sc2[i][j] = 0ull;
#pragma unroll 4
                for (int d2 = 0; d2 < 16; d2++) {
                    u64 q0 = lds64(qr0 + 2 * d2);
                    u64 q1 = lds64(qr1 + 2 * d2);
#pragma unroll
                    for (int j = 0; j < 8; j++) {
                        u64 kv = lds64(kh + (dc * 8 + j) * SCS + 2 * d2);
                        fma2(sc2[0][j], q0, kv);
                        fma2(sc2[1][j], q1, kv);
                    }
                }
                float sc[2][8];
#pragma unroll
                for (int i = 0; i < 2; i++)
#pragma unroll
                    for (int j = 0; j < 8; j++) {
                        float lo, hi; upk2(lo, hi, sc2[i][j]); sc[i][j] = lo + hi;
                    }
#pragma unroll
                for (int i = 0; i < 2; i++) {
                    float mx = -1e30f;
#pragma unroll
                    for (int j = 0; j < 8; j++) { sc[i][j] *= inv_t; mx = fmaxf(mx, sc[i][j]); }
                    mx = fmaxf(mx, __shfl_xor_sync(0xffffffffu, mx, 1));
                    mx = fmaxf(mx, __shfl_xor_sync(0xffffffffu, mx, 2));
                    float sum = 0.f;
#pragma unroll
                    for (int j = 0; j < 8; j++) { sc[i][j] = __expf(sc[i][j] - mx); sum += sc[i][j]; }
                    sum += __shfl_xor_sync(0xffffffffu, sum, 1);
                    sum += __shfl_xor_sync(0xffffffffu, sum, 2);
                    float inv = 1.f / sum;
#pragma unroll
                    for (int j = 0; j < 8; j++) sc[i][j] *= inv;
                }
                // attn -> qh rows (each lane its own rows)
#pragma unroll
                for (int i = 0; i < 2; i++)
#pragma unroll
                    for (int j = 0; j < 8; j++)
                        qh[(qbase + tr + 8 * i) * SCS + dc * 8 + j] = sc[i][j];
                __syncwarp();
                u64 av2[2][4];
#pragma unroll
                for (int i = 0; i < 2; i++)
#pragma unroll
                    for (int jp = 0; jp < 4; jp++) av2[i][jp] = 0ull;
#pragma unroll 4
                for (int k2 = 0; k2 < 32; k2++) {
                    u64 a0 = dup2(qr0[k2]);
                    u64 a1 = dup2(qr1[k2]);
#pragma unroll
                    for (int jp = 0; jp < 4; jp++) {
                        u64 vv = lds64(vh + k2 * SCS + dc * 8 + 2 * jp);
                        fma2(av2[0][jp], a0, vv);
                        fma2(av2[1][jp], a1, vv);
                    }
                }
                const int h = p * 4 + hl;
#pragma unroll
                for (int i = 0; i < 2; i++)
#pragma unroll
                    for (int jp = 0; jp < 4; jp++)
                        *reinterpret_cast<u64*>(gatt + (qbase + tr + 8 * i) * 512
                                                + h * 32 + dc * 8 + 2 * jp) = av2[i][jp];
            }
        }
    }

    // ============ Phase 3: stage ATT from gmem, proj with transposed weights ============
    __syncthreads();
    for (int i = tid; i < 16384; i += NT)
        s[OFF_ATT + (i >> 9) * 516 + (i & 511)] = gatt[i];
    for (int i = tid; i < 32 * 12; i += NT) {
        int t = i / 12, j = i % 12;
        s[OFF_Y + t * 140 + (j < 6 ? j : j + 128)] = 0.f;
    }
    __syncthreads();
    {
        const int tq = lane >> 4, ml = lane & 15;
        const int m0 = (w >> 2) * 64 + ml * 4;      // 4 m's per thread
        const int tb = (w & 3) * 8 + tq * 4;        // 4 t-rows per thread
        u64 acc[4][2];
#pragma unroll
        for (int t = 0; t < 4; t++) { acc[t][0] = 0ull; acc[t][1] = 0ull; }
        const float* bp0 = g_pwT + m0;
        ulonglong2 c0 = __ldg((const ulonglong2*)bp0);
        ulonglong2 c1 = __ldg((const ulonglong2*)(bp0 + 128));
#pragma unroll 2
        for (int j2 = 0; j2 < 256; j2++) {                   // FULL 512 reduction (2 j per iter)
            const int nj = (j2 < 255) ? (2 * j2 + 2) : 510;
            ulonglong2 n0 = __ldg((const ulonglong2*)(bp0 + nj * 128));
            ulonglong2 n1 = __ldg((const ulonglong2*)(bp0 + (nj + 1) * 128));
#pragma unroll
            for (int t = 0; t < 4; t++) {
                u64 a01 = lds64(s + OFF_ATT + (tb + t) * 516 + 2 * j2);
                float alo, ahi; upk2(alo, ahi, a01);
                u64 d0 = dup2(alo), d1 = dup2(ahi);
                fma2(acc[t][0], d0, c0.x); fma2(acc[t][1], d0, c0.y);
                fma2(acc[t][0], d1, c1.x); fma2(acc[t][1], d1, c1.y);
            }
            c0 = n0; c1 = n1;
        }
        float4 bb = __ldg((const float4*)(proj_b + m0));
#pragma unroll
        for (int t = 0; t < 4; t++) {
            float y0, y1, y2, y3;
            upk2(y0, y1, acc[t][0]);
            upk2(y2, y3, acc[t][1]);
            float* yp = s + OFF_Y + (tb + t) * 140 + 6 + m0;
            *reinterpret_cast<u64*>(yp)     = pk2(y0 + bb.x, y1 + bb.y);
            *reinterpret_cast<u64*>(yp + 2) = pk2(y2 + bb.z, y3 + bb.w);
        }
    }
    __syncthreads();

    // ============ Phase 4: final conv (32->64, kw13) + residual ============
    {
        const int co = (tid >> 3) * 2;    // 0,2,..,62 : this thread co, co+1
        const int l0 = (tid & 7) * 16;
        float acc[2][16];
        {
            float b0 = __ldg(&fc_b[co]), b1 = __ldg(&fc_b[co + 1]);
#pragma unroll
            for (int i = 0; i < 16; i++) { acc[0][i] = b0; acc[1][i] = b1; }
        }
#pragma unroll 1
        for (int c = 0; c < 4; c++) {
            const int ci0 = c * 8;
            __syncthreads();
            for (int i = tid; i < 64 * 8 * 13; i += NT) {
                int coi = i / 104, r = i % 104, ci = r / 13, kk = r % 13;
                s[OFF_FCW + (coi * 8 + ci) * 14 + kk] = fc_w[(coi * 32 + ci0 + ci) * 13 + kk];
            }
            __syncthreads();
#pragma unroll 1
            for (int ci = 0; ci < 8; ci++) {
                const float* xp = s + OFF_Y + (ci0 + ci) * 140 + l0;
                float xw[28];
#pragma unroll
                for (int q4 = 0; q4 < 7; q4++) {
                    float4 t4 = *(const float4*)(xp + q4 * 4);
                    xw[q4 * 4 + 0] = t4.x; xw[q4 * 4 + 1] = t4.y;
                    xw[q4 * 4 + 2] = t4.z; xw[q4 * 4 + 3] = t4.w;
                }
#pragma unroll
                for (int c2 = 0; c2 < 2; c2++) {
                    const float* wr = s + OFF_FCW + ((co + c2) * 8 + ci) * 14;
                    float wk[13];
#pragma unroll
                    for (int t = 0; t < 6; t++) {
                        float lo, hi; upk2(lo, hi, lds64(wr + 2 * t));
                        wk[2 * t] = lo; wk[2 * t + 1] = hi;
                    }
                    wk[12] = wr[12];
#pragma unroll
                    for (int kk = 0; kk < 13; kk++) {
                        float wv = wk[kk];
#pragma unroll
                        for (int i = 0; i < 16; i++)
                            acc[c2][i] = fmaf(xw[i + kk], wv, acc[c2][i]);
                    }
                }
            }
        }
        const float* qres = gq + boff;
#pragma unroll
        for (int c2 = 0; c2 < 2; c2++)
#pragma unroll
            for (int q4 = 0; q4 < 4; q4++) {
                float4 r = __ldg((const float4*)(qres + (co + c2) * 128 + l0 + q4 * 4));
                *(float4*)(s + OFF_Z + (co + c2) * 128 + l0 + q4 * 4) =
                    make_float4(acc[c2][q4 * 4] + r.x, acc[c2][q4 * 4 + 1] + r.y,
                                acc[c2][q4 * 4 + 2] + r.z, acc[c2][q4 * 4 + 3] + r.w);
            }
    }
    __syncthreads();

    // ============ Phase 5: LayerNorm (unbiased std, /(sigma+eps)) ============
    {
#pragma unroll
        for (int it = 0; it < 8; it++) {
            int r = w + it * 8;
            const float* zr = s + OFF_Z + r * 128;
            float v0 = zr[lane], v1 = zr[lane + 32], v2 = zr[lane + 64], v3 = zr[lane + 96];
            float sm = v0 + v1 + v2 + v3;
#pragma unroll
            for (int o = 16; o > 0; o >>= 1) sm += __shfl_xor_sync(0xffffffffu, sm, o);
            float mu = sm * (1.f / 128.f);
            float d0 = v0 - mu, d1 = v1 - mu, d2 = v2 - mu, d3 = v3 - mu;
            float s2 = d0 * d0 + d1 * d1 + d2 * d2 + d3 * d3;
#pragma unroll
            for (int o = 16; o > 0; o >>= 1) s2 += __shfl_xor_sync(0xffffffffu, s2, o);
            float sigma = sqrtf(s2 * (1.f / 127.f));
            float inv = 1.f / (sigma + 1e-3f);
            float* orow = out + boff + r * 128;
            orow[lane]      = d0 * inv * __ldg(&ln_a[lane])      + __ldg(&ln_b[lane]);
            orow[lane + 32] = d1 * inv * __ldg(&ln_a[lane + 32]) + __ldg(&ln_b[lane + 32]);
            orow[lane + 64] = d2 * inv * __ldg(&ln_a[lane + 64]) + __ldg(&ln_b[lane + 64]);
            orow[lane + 96] = d3 * inv * __ldg(&ln_a[lane + 96]) + __ldg(&ln_b[lane + 96]);
        }
    }
}

extern "C" void kernel_launch(void* const* d_in, const int* in_sizes, int n_in,
                              void* d_out, int out_size)
{
    const float* q      = (const float*)d_in[0];
    const float* k      = (const float*)d_in[1];
    const float* v      = (const float*)d_in[2];
    const float* cq_w   = (const float*)d_in[3];
    const float* cq_b   = (const float*)d_in[4];
    const float* ck_w   = (const float*)d_in[5];
    const float* ck_b   = (const float*)d_in[6];
    const float* cv_w   = (const float*)d_in[7];
    const float* cv_b   = (const float*)d_in[8];
    const float* w_qs   = (const float*)d_in[9];
    const float* w_ks   = (const float*)d_in[10];
    const float* w_vs   = (const float*)d_in[11];
    const float* proj_w = (const float*)d_in[12];
    const float* proj_b = (const float*)d_in[13];
    const float* fc_w   = (const float*)d_in[14];
    const float* fc_b   = (const float*)d_in[15];
    const float* ln_a   = (const float*)d_in[16];
    const float* ln_b   = (const float*)d_in[17];
    float* outp = (float*)d_out;

    const int B = in_sizes[0] / (64 * 128);

    transpose_pw_kernel<<<128, 512>>>(proj_w);

    cudaFuncSetAttribute(ha_kernel, cudaFuncAttributeMaxDynamicSharedMemorySize, SMEM_BYTES);
    ha_kernel<<<B, NT, SMEM_BYTES>>>(q, k, v, cq_w, cq_b, ck_w, ck_b, cv_w, cv_b,
                                     w_qs, w_ks, w_vs, proj_w, proj_b, fc_w, fc_b,
                                     ln_a, ln_b, outp);
}